// round 5
// baseline (speedup 1.0000x reference)
#include <cuda_runtime.h>
#include <cstdint>

#define BB    16
#define CINC  128
#define CCW   32     // cin / kappa (weight channels)
#define RSTR  37     // smem row stride (conflict-free)
#define UROWS 34     // rows 0..33 (rows 32,33 = zero pad)
#define USTRIDE (UROWS * RSTR)          // 1258 floats per channel plane
#define WF_U64  (CCW * 9 * 8)           // 2304 weight pairs (u64 each)
#define SMEM_BYTES (WF_U64 * 8 + CCW * USTRIDE * 4)   // 18432 + 161024 = 179456
#define NT 512

__device__ __forceinline__ unsigned long long fdup(float x) {
    unsigned long long r; unsigned u = __float_as_uint(x);
    asm("mov.b64 %0, {%1,%2};" : "=l"(r) : "r"(u), "r"(u));
    return r;
}
__device__ __forceinline__ unsigned long long fma2(unsigned long long a,
                                                   unsigned long long b,
                                                   unsigned long long c) {
    unsigned long long d;
    asm("fma.rn.f32x2 %0, %1, %2, %3;" : "=l"(d) : "l"(a), "l"(b), "l"(c));
    return d;
}

__global__ void __launch_bounds__(NT, 1)
fconv_kernel(const float* __restrict__ x, const float* __restrict__ w,
             float* __restrict__ out) {
    const int dg  = blockIdx.x;   // d-group 0..8
    const int b   = blockIdx.y;   // batch
    const int tid = threadIdx.x;

    extern __shared__ unsigned char smraw[];
    unsigned long long* wf = (unsigned long long*)smraw;   // [cc][t][j][np] pairs
    float* u = (float*)(smraw + WF_U64 * 8);               // [32][34][37]

    // ---- build flipped weight pairs: wf[cc][t][j][np] = (w[2np,cc,2-t,2-j], w[2np+1,...]) ----
    for (int p = tid; p < WF_U64; p += NT) {
        int np = p & 7;
        int rem = p >> 3;
        int j  = rem % 3;
        int t  = (rem / 3) % 3;
        int cc = rem / 9;
        int base = cc * 9 + (2 - t) * 3 + (2 - j);
        float w0 = w[(2 * np)     * 288 + base];
        float w1 = w[(2 * np + 1) * 288 + base];
        ((float2*)wf)[p] = make_float2(w0, w1);   // low = even n
    }

    // ---- selective zero: pad cols 32..36 (all 34 rows), rows 32..33 cols 0..31 ----
    for (int i = tid; i < CCW * UROWS * 5; i += NT) {
        int c5 = i % 5;
        int rr = (i / 5) % UROWS;
        int cc = i / (5 * UROWS);
        u[cc * USTRIDE + rr * RSTR + 32 + c5] = 0.0f;
    }
    for (int i = tid; i < CCW * 2 * 32; i += NT) {
        int c  = i & 31;
        int rr = 32 + ((i >> 5) & 1);
        int cc = i >> 6;
        u[cc * USTRIDE + rr * RSTR + c] = 0.0f;
    }

    // ---- load u[cc][r] = 0.5*(x[(8dg-cc)%128] + x[(-8dg-cc)%128]), rows 0..31 ----
    // thread -> fixed (cc, c4, row-half): 17 rows each... rows 0..31 only (32,33 zeroed)
    {
        const int m  = dg * 8;
        const int cc = tid >> 4;          // 0..31
        const int c4 = tid & 7;           // 0..7 (float4 col)
        const int rh = (tid >> 3) & 1;    // row half
        const int ca = (m - cc + 128) & 127;
        const int cb = (256 - m - cc) & 127;
        const float4* xa = (const float4*)(x + ((size_t)b * CINC + ca) * 1024) + c4;
        const float4* xb = (const float4*)(x + ((size_t)b * CINC + cb) * 1024) + c4;
        float* d = u + cc * USTRIDE + c4 * 4;
#pragma unroll
        for (int r0 = 0; r0 < 16; ++r0) {
            int r = rh * 16 + r0;
            float4 va = xa[r * 8];
            float4 vb = xb[r * 8];
            float* dr = d + r * RSTR;     // odd stride -> scalar stores
            dr[0] = 0.5f * (va.x + vb.x);
            dr[1] = 0.5f * (va.y + vb.y);
            dr[2] = 0.5f * (va.z + vb.z);
            dr[3] = 0.5f * (va.w + vb.w);
        }
    }
    __syncthreads();

    // ---- main loop: each thread computes 4 spatial cols x 8 n outputs ----
    const int lho = tid >> 4;            // 0..31
    const int cg  = (tid >> 1) & 7;      // col group: wo = cg*4
    const int ng  = tid & 1;             // n half: np in [4*ng, 4*ng+4)
    const int wo  = cg << 2;

    unsigned long long acc[4][4];        // [np][col]
#pragma unroll
    for (int a = 0; a < 4; a++)
#pragma unroll
        for (int s = 0; s < 4; s++) acc[a][s] = 0ull;

    const float* ub = u + lho * RSTR + wo;
    const int ng2 = ng << 1;

#pragma unroll 2
    for (int cc = 0; cc < CCW; ++cc) {
        const float* up = ub + cc * USTRIDE;
        const ulonglong2* wp = (const ulonglong2*)(wf + cc * 72);
#pragma unroll
        for (int t = 0; t < 3; t++) {
            unsigned long long xd[6];
#pragma unroll
            for (int q = 0; q < 6; q++) xd[q] = fdup(up[t * RSTR + q]);
#pragma unroll
            for (int j = 0; j < 3; j++) {
                ulonglong2 wA = wp[(t * 3 + j) * 4 + ng2 + 0];
                ulonglong2 wB = wp[(t * 3 + j) * 4 + ng2 + 1];
                unsigned long long wv[4] = {wA.x, wA.y, wB.x, wB.y};
#pragma unroll
                for (int np = 0; np < 4; np++) {
#pragma unroll
                    for (int s = 0; s < 4; s++)
                        acc[np][s] = fma2(wv[np], xd[j + s], acc[np][s]);
                }
            }
        }
    }

    // ---- epilogue: write d-group dg, duplicate to 16-dg for dg in 1..7 ----
    const int nb = ng << 3;              // n base: 0 or 8
    float* o1 = out + (((size_t)b * 256 + dg * 16 + nb)) * 1024 + lho * 32 + wo;
    float* o2 = out + (((size_t)b * 256 + (16 - dg) * 16 + nb)) * 1024 + lho * 32 + wo;
    const bool dup = (dg >= 1 && dg <= 7);

#pragma unroll
    for (int np = 0; np < 4; np++) {
        float4 v0, v1;
        v0.x = __uint_as_float((unsigned)acc[np][0]);
        v0.y = __uint_as_float((unsigned)acc[np][1]);
        v0.z = __uint_as_float((unsigned)acc[np][2]);
        v0.w = __uint_as_float((unsigned)acc[np][3]);
        v1.x = __uint_as_float((unsigned)(acc[np][0] >> 32));
        v1.y = __uint_as_float((unsigned)(acc[np][1] >> 32));
        v1.z = __uint_as_float((unsigned)(acc[np][2] >> 32));
        v1.w = __uint_as_float((unsigned)(acc[np][3] >> 32));
        *(float4*)(o1 + (size_t)(2 * np)     * 1024) = v0;
        *(float4*)(o1 + (size_t)(2 * np + 1) * 1024) = v1;
        if (dup) {
            *(float4*)(o2 + (size_t)(2 * np)     * 1024) = v0;
            *(float4*)(o2 + (size_t)(2 * np + 1) * 1024) = v1;
        }
    }
}

extern "C" void kernel_launch(void* const* d_in, const int* in_sizes, int n_in,
                              void* d_out, int out_size) {
    const float* x = (const float*)d_in[0];
    const float* w = (const float*)d_in[1];
    float* out = (float*)d_out;

    cudaFuncSetAttribute(fconv_kernel,
                         cudaFuncAttributeMaxDynamicSharedMemorySize, SMEM_BYTES);

    dim3 grid(9, BB);   // 144 CTAs = one wave
    fconv_kernel<<<grid, NT, SMEM_BYTES>>>(x, w, out);
}

// round 7
// speedup vs baseline: 1.1337x; 1.1337x over previous
#include <cuda_runtime.h>
#include <cstdint>

#define BB    16
#define CINC  128
#define CCW   32     // cin / kappa (weight channels)
#define RSTR  37     // smem row stride (conflict-free)
#define UROWS 34     // rows 0..33 (rows 32,33 = zero pad)
#define USTRIDE (UROWS * RSTR)          // 1258 floats per channel plane
#define WF_U64  (CCW * 9 * 8)           // 2304 weight pairs (u64 each)
#define SMEM_BYTES (WF_U64 * 8 + CCW * USTRIDE * 4)   // 18432 + 161024 = 179456
#define NT 512

__device__ __forceinline__ unsigned long long fdup(float x) {
    unsigned long long r; unsigned u = __float_as_uint(x);
    asm("mov.b64 %0, {%1,%2};" : "=l"(r) : "r"(u), "r"(u));
    return r;
}
__device__ __forceinline__ unsigned long long fma2(unsigned long long a,
                                                   unsigned long long b,
                                                   unsigned long long c) {
    unsigned long long d;
    asm("fma.rn.f32x2 %0, %1, %2, %3;" : "=l"(d) : "l"(a), "l"(b), "l"(c));
    return d;
}

__global__ void __launch_bounds__(NT, 1)
fconv_kernel(const float* __restrict__ x, const float* __restrict__ w,
             float* __restrict__ out) {
    const int dg  = blockIdx.x;   // d-group 0..8
    const int b   = blockIdx.y;   // batch
    const int tid = threadIdx.x;

    extern __shared__ unsigned char smraw[];
    unsigned long long* wf = (unsigned long long*)smraw;   // [cc][t][j][np] pairs
    float* u = (float*)(smraw + WF_U64 * 8);               // [32][34][37]

    // ---- build flipped weight pairs: wf[cc][t][j][np] = (w[2np,cc,2-t,2-j], w[2np+1,...]) ----
    for (int p = tid; p < WF_U64; p += NT) {
        int np = p & 7;
        int rem = p >> 3;
        int j  = rem % 3;
        int t  = (rem / 3) % 3;
        int cc = rem / 9;
        int base = cc * 9 + (2 - t) * 3 + (2 - j);
        float w0 = w[(2 * np)     * 288 + base];
        float w1 = w[(2 * np + 1) * 288 + base];
        ((float2*)wf)[p] = make_float2(w0, w1);   // low = even n
    }

    // ---- selective zero: pad cols 32..36 (all 34 rows), rows 32..33 cols 0..31 ----
    for (int i = tid; i < CCW * UROWS * 5; i += NT) {
        int c5 = i % 5;
        int rr = (i / 5) % UROWS;
        int cc = i / (5 * UROWS);
        u[cc * USTRIDE + rr * RSTR + 32 + c5] = 0.0f;
    }
    for (int i = tid; i < CCW * 2 * 32; i += NT) {
        int c  = i & 31;
        int rr = 32 + ((i >> 5) & 1);
        int cc = i >> 6;
        u[cc * USTRIDE + rr * RSTR + c] = 0.0f;
    }

    // ---- load u[cc][r] = 0.5*(x[(8dg-cc)%128] + x[(-8dg-cc)%128]), rows 0..31 ----
    // thread -> fixed (cc, c4, row-half): 17 rows each... rows 0..31 only (32,33 zeroed)
    {
        const int m  = dg * 8;
        const int cc = tid >> 4;          // 0..31
        const int c4 = tid & 7;           // 0..7 (float4 col)
        const int rh = (tid >> 3) & 1;    // row half
        const int ca = (m - cc + 128) & 127;
        const int cb = (256 - m - cc) & 127;
        const float4* xa = (const float4*)(x + ((size_t)b * CINC + ca) * 1024) + c4;
        const float4* xb = (const float4*)(x + ((size_t)b * CINC + cb) * 1024) + c4;
        float* d = u + cc * USTRIDE + c4 * 4;
#pragma unroll
        for (int r0 = 0; r0 < 16; ++r0) {
            int r = rh * 16 + r0;
            float4 va = xa[r * 8];
            float4 vb = xb[r * 8];
            float* dr = d + r * RSTR;     // odd stride -> scalar stores
            dr[0] = 0.5f * (va.x + vb.x);
            dr[1] = 0.5f * (va.y + vb.y);
            dr[2] = 0.5f * (va.z + vb.z);
            dr[3] = 0.5f * (va.w + vb.w);
        }
    }
    __syncthreads();

    // ---- main loop: each thread computes 4 spatial cols x 8 n outputs ----
    const int lho = tid >> 4;            // 0..31
    const int cg  = (tid >> 1) & 7;      // col group: wo = cg*4
    const int ng  = tid & 1;             // n half: np in [4*ng, 4*ng+4)
    const int wo  = cg << 2;

    unsigned long long acc[4][4];        // [np][col]
#pragma unroll
    for (int a = 0; a < 4; a++)
#pragma unroll
        for (int s = 0; s < 4; s++) acc[a][s] = 0ull;

    const float* ub = u + lho * RSTR + wo;
    const int ng2 = ng << 1;

#pragma unroll 2
    for (int cc = 0; cc < CCW; ++cc) {
        const float* up = ub + cc * USTRIDE;
        const ulonglong2* wp = (const ulonglong2*)(wf + cc * 72);
#pragma unroll
        for (int t = 0; t < 3; t++) {
            unsigned long long xd[6];
#pragma unroll
            for (int q = 0; q < 6; q++) xd[q] = fdup(up[t * RSTR + q]);
#pragma unroll
            for (int j = 0; j < 3; j++) {
                ulonglong2 wA = wp[(t * 3 + j) * 4 + ng2 + 0];
                ulonglong2 wB = wp[(t * 3 + j) * 4 + ng2 + 1];
                unsigned long long wv[4] = {wA.x, wA.y, wB.x, wB.y};
#pragma unroll
                for (int np = 0; np < 4; np++) {
#pragma unroll
                    for (int s = 0; s < 4; s++)
                        acc[np][s] = fma2(wv[np], xd[j + s], acc[np][s]);
                }
            }
        }
    }

    // ---- epilogue: write d-group dg, duplicate to 16-dg for dg in 1..7 ----
    const int nb = ng << 3;              // n base: 0 or 8
    float* o1 = out + (((size_t)b * 256 + dg * 16 + nb)) * 1024 + lho * 32 + wo;
    float* o2 = out + (((size_t)b * 256 + (16 - dg) * 16 + nb)) * 1024 + lho * 32 + wo;
    const bool dup = (dg >= 1 && dg <= 7);

#pragma unroll
    for (int np = 0; np < 4; np++) {
        float4 v0, v1;
        v0.x = __uint_as_float((unsigned)acc[np][0]);
        v0.y = __uint_as_float((unsigned)acc[np][1]);
        v0.z = __uint_as_float((unsigned)acc[np][2]);
        v0.w = __uint_as_float((unsigned)acc[np][3]);
        v1.x = __uint_as_float((unsigned)(acc[np][0] >> 32));
        v1.y = __uint_as_float((unsigned)(acc[np][1] >> 32));
        v1.z = __uint_as_float((unsigned)(acc[np][2] >> 32));
        v1.w = __uint_as_float((unsigned)(acc[np][3] >> 32));
        *(float4*)(o1 + (size_t)(2 * np)     * 1024) = v0;
        *(float4*)(o1 + (size_t)(2 * np + 1) * 1024) = v1;
        if (dup) {
            *(float4*)(o2 + (size_t)(2 * np)     * 1024) = v0;
            *(float4*)(o2 + (size_t)(2 * np + 1) * 1024) = v1;
        }
    }
}

extern "C" void kernel_launch(void* const* d_in, const int* in_sizes, int n_in,
                              void* d_out, int out_size) {
    const float* x = (const float*)d_in[0];
    const float* w = (const float*)d_in[1];
    float* out = (float*)d_out;

    cudaFuncSetAttribute(fconv_kernel,
                         cudaFuncAttributeMaxDynamicSharedMemorySize, SMEM_BYTES);

    dim3 grid(9, BB);   // 144 CTAs = one wave
    fconv_kernel<<<grid, NT, SMEM_BYTES>>>(x, w, out);
}

// round 11
// speedup vs baseline: 1.4233x; 1.2554x over previous
#include <cuda_runtime.h>
#include <cstdint>

#define A_ROWS   1160
#define A_BYTES  (A_ROWS * 128)           // 148480
#define B_OFF    A_BYTES
#define B_BYTES  (9 * 32 * 128)           // 36864
#define SMEM_TOTAL (B_OFF + B_BYTES)      // 185344

#define SW(o) ((o) ^ (((o) >> 3) & 0x70))

__device__ __forceinline__ uint32_t smem_u32(const void* p) {
    uint32_t a;
    asm("{ .reg .u64 t; cvta.to.shared.u64 t, %1; cvt.u32.u64 %0, t; }" : "=r"(a) : "l"(p));
    return a;
}
__device__ __forceinline__ uint32_t f2bf(float f) {
    uint32_t u = __float_as_uint(f);
    return (u + 0x7FFFu + ((u >> 16) & 1u)) >> 16;
}
__device__ __forceinline__ float bf2f(uint32_t b) { return __uint_as_float(b << 16); }
__device__ __forceinline__ void sts32(uint32_t addr, uint32_t v) {
    asm volatile("st.shared.b32 [%0], %1;" :: "r"(addr), "r"(v) : "memory");
}
__device__ __forceinline__ void ldsm4(uint32_t* r, uint32_t addr) {
    asm volatile("ldmatrix.sync.aligned.m8n8.x4.shared.b16 {%0,%1,%2,%3}, [%4];"
                 : "=r"(r[0]), "=r"(r[1]), "=r"(r[2]), "=r"(r[3]) : "r"(addr));
}
__device__ __forceinline__ void mma16816(float* d, const uint32_t* a,
                                         uint32_t b0, uint32_t b1) {
    asm volatile(
        "mma.sync.aligned.m16n8k16.row.col.f32.bf16.bf16.f32 "
        "{%0,%1,%2,%3}, {%4,%5,%6,%7}, {%8,%9}, {%0,%1,%2,%3};"
        : "+f"(d[0]), "+f"(d[1]), "+f"(d[2]), "+f"(d[3])
        : "r"(a[0]), "r"(a[1]), "r"(a[2]), "r"(a[3]), "r"(b0), "r"(b1));
}

template<int TILES>
__device__ __forceinline__ void gemm_tiles(uint32_t base, int m0base, int lane,
                                           float* o1, float* o2, bool dup) {
    float acc[TILES][4][4];
#pragma unroll
    for (int t = 0; t < TILES; t++)
#pragma unroll
        for (int n = 0; n < 4; n++)
#pragma unroll
            for (int k = 0; k < 4; k++) acc[t][n][k] = 0.0f;

    // per-lane logical offset pieces
    const int arow_l = lane & 15;                 // A row within tile
    const int acol_l = (lane >> 4) * 16;          // A 16B col select
    const int bn_l   = (((lane >> 4) << 3) | (lane & 7)) * 128 + ((lane >> 3) & 1) * 16;

#pragma unroll 1
    for (int tap = 0; tap < 9; tap++) {
        const int sh = (tap / 3) * 34 + (tap % 3);
        int arow_off[TILES];
#pragma unroll
        for (int tt = 0; tt < TILES; tt++)
            arow_off[tt] = (m0base + tt * 16 + sh + arow_l) * 128 + acol_l;
        const int bbase = tap * 4096 + bn_l;

#pragma unroll
        for (int ks = 0; ks < 4; ks++) {
            uint32_t b[8];
            uint32_t ba = base + B_OFF + (uint32_t)SW(bbase + ks * 32);
            ldsm4(b, ba);                 // ntiles 0,1 (n 0..15)
            ldsm4(b + 4, ba + 2048);      // ntiles 2,3 (n 16..31)
#pragma unroll
            for (int tt = 0; tt < TILES; tt++) {
                uint32_t a[4];
                ldsm4(a, base + (uint32_t)SW(arow_off[tt] + ks * 32));
                mma16816(acc[tt][0], a, b[0], b[1]);
                mma16816(acc[tt][1], a, b[2], b[3]);
                mma16816(acc[tt][2], a, b[4], b[5]);
                mma16816(acc[tt][3], a, b[6], b[7]);
            }
        }
    }

    // epilogue: out n = D[n] + D[n+16]
    const int n0 = (lane & 3) * 2;
#pragma unroll
    for (int tt = 0; tt < TILES; tt++) {
        const int rlo = m0base + tt * 16 + (lane >> 2);
        const int rhi = rlo + 8;
#pragma unroll
        for (int half = 0; half < 2; half++) {      // d0,d1 = rlo ; d2,d3 = rhi
            const int row = half ? rhi : rlo;
            const int h = row / 34;
            const int wc = row - h * 34;
            if (wc < 32) {
                const int sp = h * 32 + wc;
#pragma unroll
                for (int nt = 0; nt < 2; nt++) {    // n-group 0..7 / 8..15
#pragma unroll
                    for (int e = 0; e < 2; e++) {
                        float v = acc[tt][nt][half * 2 + e] + acc[tt][nt + 2][half * 2 + e];
                        int n = nt * 8 + n0 + e;
                        o1[(size_t)n * 1024 + sp] = v;
                        if (dup) o2[(size_t)n * 1024 + sp] = v;
                    }
                }
            }
        }
    }
}

__global__ void __launch_bounds__(512, 1)
fconv_mma(const float* __restrict__ x, const float* __restrict__ w,
          float* __restrict__ out) {
    const int dg  = blockIdx.x;          // 0..8
    const int b   = blockIdx.y;
    const int tid = threadIdx.x;
    const int wid = tid >> 5;
    const int lane = tid & 31;

    extern __shared__ unsigned char smraw[];
    const uint32_t base = smem_u32(smraw);

    // ---- zero pad rows: w in {32,33} for h<32 (64 rows) + rows [1088,1160) (72) ----
    for (int idx = tid; idx < 136 * 8; idx += 512) {
        int row = idx >> 3, c = idx & 7;
        int m = (row < 64) ? ((row >> 1) * 34 + 32 + (row & 1)) : (1088 + row - 64);
        asm volatile("st.shared.v4.b32 [%0], {%1,%1,%1,%1};"
                     :: "r"(base + (uint32_t)(m * 128 + c * 16)), "r"(0u) : "memory");
    }

    // ---- build B: [tap][n][k]; n<16:(w_hi,w_hi), n>=16:(w_lo,0) ----
    for (int idx = tid; idx < 9216; idx += 512) {
        int tap = idx >> 10, rem = idx & 1023;
        int n = rem >> 5, cc = rem & 31;
        int t = tap / 3, j = tap % 3;
        int wbase = cc * 9 + (2 - t) * 3 + (2 - j);
        uint32_t pack;
        if (n < 16) {
            uint32_t hb = f2bf(w[n * 288 + wbase]);
            pack = hb | (hb << 16);
        } else {
            float v = w[(n - 16) * 288 + wbase];
            uint32_t hb = f2bf(v);
            pack = f2bf(v - bf2f(hb));
        }
        sts32(base + B_OFF + tap * 4096 + (uint32_t)SW(n * 128 + cc * 4), pack);
    }

    // ---- build A: u = 0.5*(x[(8dg-cc)%128] + x[(-8dg-cc)%128]) as (hi,lo) pairs ----
    {
        const int m8 = dg * 8;
        const int cc = tid >> 4;
        const int rh = (tid >> 3) & 1;
        const int w4 = tid & 7;
        const int ca = (m8 - cc + 128) & 127;
        const int cb = (256 - m8 - cc) & 127;
        const float4* xa = (const float4*)(x + ((size_t)b * 128 + ca) * 1024) + w4;
        const float4* xb = (const float4*)(x + ((size_t)b * 128 + cb) * 1024) + w4;
#pragma unroll 4
        for (int h = rh; h < 32; h += 2) {
            float4 va = xa[h * 8];
            float4 vb = xb[h * 8];
            float uv[4] = {0.5f * (va.x + vb.x), 0.5f * (va.y + vb.y),
                           0.5f * (va.z + vb.z), 0.5f * (va.w + vb.w)};
            int m0 = h * 34 + w4 * 4;
#pragma unroll
            for (int i = 0; i < 4; i++) {
                uint32_t hb = f2bf(uv[i]);
                uint32_t lb = f2bf(uv[i] - bf2f(hb));
                sts32(base + (uint32_t)SW((m0 + i) * 128 + cc * 4), hb | (lb << 16));
            }
        }
    }
    __syncthreads();

    const bool dup = (dg >= 1 && dg <= 7);
    float* o1 = out + ((size_t)b * 256 + dg * 16) * 1024;
    float* o2 = out + ((size_t)b * 256 + (16 - dg) * 16) * 1024;

    // 64 tiles: 4 consecutive per warp
    gemm_tiles<4>(base, wid * 64, lane, o1, o2, dup);
    // tail tiles 64..67 on warps 0..3
    if (wid < 4)
        gemm_tiles<1>(base, 1024 + wid * 16, lane, o1, o2, dup);
}

extern "C" void kernel_launch(void* const* d_in, const int* in_sizes, int n_in,
                              void* d_out, int out_size) {
    const float* x = (const float*)d_in[0];
    const float* w = (const float*)d_in[1];
    float* out = (float*)d_out;

    cudaFuncSetAttribute(fconv_mma,
                         cudaFuncAttributeMaxDynamicSharedMemorySize, SMEM_TOTAL);

    dim3 grid(9, 16);   // 144 CTAs = one wave
    fconv_mma<<<grid, 512, SMEM_TOTAL>>>(x, w, out);
}